// round 5
// baseline (speedup 1.0000x reference)
#include <cuda_runtime.h>
#include <math.h>

#define B_  2
#define S_  2048
#define D_  1024
#define H_  16
#define HD_ 64

// ---------------- scratch (no allocs allowed) ----------------
__device__ float g_q[B_*H_*S_*HD_];
__device__ float g_k[B_*H_*S_*HD_];
__device__ float g_v[B_*H_*S_*HD_];
__device__ float g_cos[S_*(HD_/2)];
__device__ float g_sin[S_*(HD_/2)];

// ---------------- helpers ----------------
__device__ __forceinline__ unsigned f2tf(float f) {
    unsigned u;
    asm("cvt.rna.tf32.f32 %0, %1;" : "=r"(u) : "f"(f));
    return u;
}

__device__ __forceinline__ void mma8(float* c, const unsigned* a, const unsigned* b) {
    asm volatile(
        "mma.sync.aligned.m16n8k8.row.col.f32.tf32.tf32.f32 "
        "{%0,%1,%2,%3},{%4,%5,%6,%7},{%8,%9},{%0,%1,%2,%3};"
        : "+f"(c[0]), "+f"(c[1]), "+f"(c[2]), "+f"(c[3])
        : "r"(a[0]), "r"(a[1]), "r"(a[2]), "r"(a[3]),
          "r"(b[0]), "r"(b[1]));
}

__device__ __forceinline__ void cpa16(void* smem, const void* gmem) {
    unsigned s = (unsigned)__cvta_generic_to_shared(smem);
    asm volatile("cp.async.cg.shared.global [%0], [%1], 16;" :: "r"(s), "l"(gmem));
}
#define CPA_COMMIT() asm volatile("cp.async.commit_group;")
#define CPA_WAIT0()  asm volatile("cp.async.wait_group 0;")

// convert 16B chunk of fp32 in smem to tf32 in place
__device__ __forceinline__ void cvt_chunk(unsigned* p) {
    float4 v = *(const float4*)p;
    uint4 u = { f2tf(v.x), f2tf(v.y), f2tf(v.z), f2tf(v.w) };
    *(uint4*)p = u;
}

// ---------------- RoPE table ----------------
__global__ void rope_table_kernel() {
    int idx = blockIdx.x * blockDim.x + threadIdx.x;
    if (idx < S_ * (HD_/2)) {
        int s = idx >> 5;
        int p = idx & 31;
        double theta = exp2(-(double)p * (13.287712379549449 / 32.0));
        double ang = (double)s * theta;
        const double twopi = 6.283185307179586476925286766559;
        double r = ang - twopi * floor(ang / twopi);
        float sn, cs;
        sincosf((float)r, &sn, &cs);
        g_cos[idx] = cs;
        g_sin[idx] = sn;
    }
}

// ---------------- QKV GEMM (tf32 mma, cp.async double-buffered) ----------------
// 128x128 tile, BK=16, 256 threads = 8 warps, warp tile 64x32 (4 m16 x 4 n8).
#define GSTR 20

__global__ __launch_bounds__(256, 2) void qkv_gemm_kernel(
    const float* __restrict__ x,
    const float* __restrict__ wq, const float* __restrict__ bq,
    const float* __restrict__ wk, const float* __restrict__ bk,
    const float* __restrict__ wv, const float* __restrict__ bv)
{
    const int mat = blockIdx.z;
    const float* __restrict__ W    = (mat==0) ? wq : (mat==1 ? wk : wv);
    const float* __restrict__ bias = (mat==0) ? bq : (mat==1 ? bk : bv);
    float* out = (mat==0) ? g_q : (mat==1 ? g_k : g_v);

    __shared__ unsigned As[2][128*GSTR];
    __shared__ unsigned Bs[2][128*GSTR];

    const int tid  = threadIdx.x;
    const int warp = tid >> 5;
    const int lane = tid & 31;
    const int g    = lane >> 2;
    const int tg   = lane & 3;
    const int wm   = warp & 1;
    const int wn   = warp >> 1;

    const int m0 = blockIdx.y * 128;
    const int n0 = blockIdx.x * 128;

    int am[2], ac[2];
    {
        int f0 = tid;       am[0] = f0 >> 2; ac[0] = (f0 & 3) * 4;
        int f1 = tid + 256; am[1] = f1 >> 2; ac[1] = (f1 & 3) * 4;
    }
    const float* aG[2] = { x + (size_t)(m0 + am[0])*D_ + ac[0],
                           x + (size_t)(m0 + am[1])*D_ + ac[1] };
    const float* bG[2] = { W + (size_t)(n0 + am[0])*D_ + ac[0],
                           W + (size_t)(n0 + am[1])*D_ + ac[1] };

    float acc[4][4][4];
    #pragma unroll
    for (int i = 0; i < 4; i++)
        #pragma unroll
        for (int j = 0; j < 4; j++)
            #pragma unroll
            for (int q = 0; q < 4; q++) acc[i][j][q] = 0.f;

    // stage 0 loads
    #pragma unroll
    for (int i = 0; i < 2; i++) {
        cpa16(&As[0][am[i]*GSTR + ac[i]], aG[i]);
        cpa16(&Bs[0][am[i]*GSTR + ac[i]], bG[i]);
    }
    CPA_COMMIT();

    int cur = 0;
    for (int k0 = 0; k0 < D_; k0 += 16) {
        CPA_WAIT0();
        __syncthreads();   // tile visible; prior compute on other buffer done

        if (k0 + 16 < D_) {
            #pragma unroll
            for (int i = 0; i < 2; i++) {
                cpa16(&As[cur^1][am[i]*GSTR + ac[i]], aG[i] + k0 + 16);
                cpa16(&Bs[cur^1][am[i]*GSTR + ac[i]], bG[i] + k0 + 16);
            }
            CPA_COMMIT();
        }

        // in-place tf32 convert of own chunks
        #pragma unroll
        for (int i = 0; i < 2; i++) {
            cvt_chunk(&As[cur][am[i]*GSTR + ac[i]]);
            cvt_chunk(&Bs[cur][am[i]*GSTR + ac[i]]);
        }
        __syncthreads();

        #pragma unroll
        for (int kk = 0; kk < 2; kk++) {
            const int k = kk * 8;
            unsigned af[4][4], bf[4][2];
            #pragma unroll
            for (int mt = 0; mt < 4; mt++) {
                int rm = wm*64 + mt*16;
                af[mt][0] = As[cur][(rm+g  )*GSTR + k + tg];
                af[mt][1] = As[cur][(rm+g+8)*GSTR + k + tg];
                af[mt][2] = As[cur][(rm+g  )*GSTR + k + tg + 4];
                af[mt][3] = As[cur][(rm+g+8)*GSTR + k + tg + 4];
            }
            #pragma unroll
            for (int nt = 0; nt < 4; nt++) {
                int cn = wn*32 + nt*8;
                bf[nt][0] = Bs[cur][(cn+g)*GSTR + k + tg];
                bf[nt][1] = Bs[cur][(cn+g)*GSTR + k + tg + 4];
            }
            #pragma unroll
            for (int mt = 0; mt < 4; mt++)
                #pragma unroll
                for (int nt = 0; nt < 4; nt++)
                    mma8(acc[mt][nt], af[mt], bf[nt]);
        }
        cur ^= 1;
    }

    // epilogue: bias + (RoPE for Q/K), scatter to [B,H,S,HD]
    #pragma unroll
    for (int mt = 0; mt < 4; mt++) {
        #pragma unroll
        for (int half = 0; half < 2; half++) {
            int r  = m0 + wm*64 + mt*16 + g + half*8;
            int b_ = r >> 11;
            int s  = r & (S_ - 1);
            #pragma unroll
            for (int nt = 0; nt < 4; nt++) {
                int n  = n0 + wn*32 + nt*8 + 2*tg;
                float c0 = acc[mt][nt][half*2]   + bias[n];
                float c1 = acc[mt][nt][half*2+1] + bias[n+1];
                int h = n >> 6;
                int d = n & 63;
                float* dst = out + ((((size_t)b_*H_ + h)*S_ + s)*HD_ + d);
                if (mat < 2) {
                    int p = d >> 1;
                    float cs = g_cos[s*32 + p];
                    float sn = g_sin[s*32 + p];
                    float2 v = { c0*cs - c1*sn, c0*sn + c1*cs };
                    *(float2*)dst = v;
                } else {
                    float2 v = { c0, c1 };
                    *(float2*)dst = v;
                }
            }
        }
    }
}

// ---------------- Flash attention (tf32 mma, double-buffered cp.async K/V) ----------------
// Block: 128 queries of one (b,h). 8 warps, each owns a 16-row slab. K tile 64.
#define PSTR 68
#define KSTR 68
#define VSTR 72
#define ATTN_SMEM_WORDS (128*PSTR + 2*64*KSTR + 2*64*VSTR)
#define ATTN_SMEM_BYTES (ATTN_SMEM_WORDS * 4)

__global__ __launch_bounds__(256, 2) void attn_kernel(float* __restrict__ out)
{
    extern __shared__ unsigned sm[];
    unsigned* Ps = sm;                              // [128][PSTR] tf32
    unsigned* Ks[2] = { Ps + 128*PSTR, Ps + 128*PSTR + 64*KSTR };
    unsigned* Vs[2] = { Ks[1] + 64*KSTR, Ks[1] + 64*KSTR + 64*VSTR };

    const int tid  = threadIdx.x;
    const int warp = tid >> 5;
    const int lane = tid & 31;
    const int g    = lane >> 2;
    const int tg   = lane & 3;
    const int qr   = warp * 16;

    const int q0 = blockIdx.x * 128;
    const int h  = blockIdx.y;
    const int b  = blockIdx.z;

    const float* qbase = g_q + (((size_t)b*H_ + h)*S_) * HD_;
    const float* kbase = g_k + (((size_t)b*H_ + h)*S_) * HD_;
    const float* vbase = g_v + (((size_t)b*H_ + h)*S_) * HD_;

    const float scale = 0.125f;

    int krow[4], kcol[4];
    #pragma unroll
    for (int r = 0; r < 4; r++) {
        int f = tid + 256*r;
        krow[r] = f >> 4;
        kcol[r] = (f & 15) * 4;
    }

    // tile 0 into buffer 0 (overlaps Q staging)
    #pragma unroll
    for (int r = 0; r < 4; r++) {
        int off = (tid + 256*r) * 4;
        cpa16(&Ks[0][krow[r]*KSTR + kcol[r]], kbase + off);
        cpa16(&Vs[0][krow[r]*VSTR + kcol[r]], vbase + off);
    }
    CPA_COMMIT();

    // ---- stage Q (scaled, tf32) into Ps, build register fragments ----
    #pragma unroll
    for (int r = 0; r < 8; r++) {
        int f   = tid + 256*r;
        int row = f >> 4;
        int col = (f & 15) * 4;
        float4 v = *(const float4*)(qbase + (size_t)(q0+row)*HD_ + col);
        uint4 u = { f2tf(v.x*scale), f2tf(v.y*scale), f2tf(v.z*scale), f2tf(v.w*scale) };
        *(uint4*)&Ps[row*PSTR + col] = u;
    }
    __syncthreads();

    unsigned qf[8][4];
    #pragma unroll
    for (int kk = 0; kk < 8; kk++) {
        qf[kk][0] = Ps[(qr+g  )*PSTR + kk*8 + tg];
        qf[kk][1] = Ps[(qr+g+8)*PSTR + kk*8 + tg];
        qf[kk][2] = Ps[(qr+g  )*PSTR + kk*8 + tg + 4];
        qf[kk][3] = Ps[(qr+g+8)*PSTR + kk*8 + tg + 4];
    }

    float o[8][4];
    #pragma unroll
    for (int nt = 0; nt < 8; nt++)
        #pragma unroll
        for (int q = 0; q < 4; q++) o[nt][q] = 0.f;
    float m0r = -INFINITY, m1r = -INFINITY, l0 = 0.f, l1 = 0.f;

    for (int kt = 0; kt < S_/64; kt++) {
        const int cur = kt & 1;
        CPA_WAIT0();
        __syncthreads();   // tile kt visible; prior compute on buffer cur done; Ps(Q) reads done

        // prefetch tile kt+1 into other buffer — overlaps all compute below
        if (kt + 1 < S_/64) {
            const float* kb = kbase + (size_t)(kt+1)*4096;
            const float* vb = vbase + (size_t)(kt+1)*4096;
            #pragma unroll
            for (int r = 0; r < 4; r++) {
                int off = (tid + 256*r) * 4;
                cpa16(&Ks[cur^1][krow[r]*KSTR + kcol[r]], kb + off);
                cpa16(&Vs[cur^1][krow[r]*VSTR + kcol[r]], vb + off);
            }
            CPA_COMMIT();
        }

        // in-place tf32 convert of own chunks
        #pragma unroll
        for (int r = 0; r < 4; r++) {
            cvt_chunk(&Ks[cur][krow[r]*KSTR + kcol[r]]);
            cvt_chunk(&Vs[cur][krow[r]*VSTR + kcol[r]]);
        }
        __syncthreads();

        // ---- S = Q K^T ----
        float s[8][4];
        #pragma unroll
        for (int nt = 0; nt < 8; nt++)
            #pragma unroll
            for (int q = 0; q < 4; q++) s[nt][q] = 0.f;

        #pragma unroll
        for (int nt = 0; nt < 8; nt++) {
            #pragma unroll
            for (int kk = 0; kk < 8; kk++) {
                unsigned bfr[2];
                bfr[0] = Ks[cur][(nt*8+g)*KSTR + kk*8 + tg];
                bfr[1] = Ks[cur][(nt*8+g)*KSTR + kk*8 + tg + 4];
                mma8(s[nt], qf[kk], bfr);
            }
        }

        // ---- online softmax ----
        float mx0 = -INFINITY, mx1 = -INFINITY;
        #pragma unroll
        for (int nt = 0; nt < 8; nt++) {
            mx0 = fmaxf(mx0, fmaxf(s[nt][0], s[nt][1]));
            mx1 = fmaxf(mx1, fmaxf(s[nt][2], s[nt][3]));
        }
        mx0 = fmaxf(mx0, __shfl_xor_sync(0xffffffffu, mx0, 1));
        mx0 = fmaxf(mx0, __shfl_xor_sync(0xffffffffu, mx0, 2));
        mx1 = fmaxf(mx1, __shfl_xor_sync(0xffffffffu, mx1, 1));
        mx1 = fmaxf(mx1, __shfl_xor_sync(0xffffffffu, mx1, 2));

        float nm0 = fmaxf(m0r, mx0), nm1 = fmaxf(m1r, mx1);
        float f0 = __expf(m0r - nm0), f1 = __expf(m1r - nm1);
        m0r = nm0; m1r = nm1;

        float rs0 = 0.f, rs1 = 0.f;
        #pragma unroll
        for (int nt = 0; nt < 8; nt++) {
            s[nt][0] = __expf(s[nt][0] - nm0);
            s[nt][1] = __expf(s[nt][1] - nm0);
            s[nt][2] = __expf(s[nt][2] - nm1);
            s[nt][3] = __expf(s[nt][3] - nm1);
            rs0 += s[nt][0] + s[nt][1];
            rs1 += s[nt][2] + s[nt][3];
            o[nt][0] *= f0; o[nt][1] *= f0;
            o[nt][2] *= f1; o[nt][3] *= f1;
        }
        rs0 += __shfl_xor_sync(0xffffffffu, rs0, 1);
        rs0 += __shfl_xor_sync(0xffffffffu, rs0, 2);
        rs1 += __shfl_xor_sync(0xffffffffu, rs1, 1);
        rs1 += __shfl_xor_sync(0xffffffffu, rs1, 2);
        l0 = l0*f0 + rs0;
        l1 = l1*f1 + rs1;

        // ---- store P (tf32) for re-fragmenting (within-warp slab only) ----
        #pragma unroll
        for (int nt = 0; nt < 8; nt++) {
            Ps[(qr+g  )*PSTR + nt*8 + 2*tg    ] = f2tf(s[nt][0]);
            Ps[(qr+g  )*PSTR + nt*8 + 2*tg + 1] = f2tf(s[nt][1]);
            Ps[(qr+g+8)*PSTR + nt*8 + 2*tg    ] = f2tf(s[nt][2]);
            Ps[(qr+g+8)*PSTR + nt*8 + 2*tg + 1] = f2tf(s[nt][3]);
        }
        __syncwarp();

        // ---- O += P V ----
        #pragma unroll
        for (int kk = 0; kk < 8; kk++) {
            unsigned pf[4];
            pf[0] = Ps[(qr+g  )*PSTR + kk*8 + tg];
            pf[1] = Ps[(qr+g+8)*PSTR + kk*8 + tg];
            pf[2] = Ps[(qr+g  )*PSTR + kk*8 + tg + 4];
            pf[3] = Ps[(qr+g+8)*PSTR + kk*8 + tg + 4];
            #pragma unroll
            for (int nt = 0; nt < 8; nt++) {
                unsigned bfr[2];
                bfr[0] = Vs[cur][(kk*8+tg  )*VSTR + nt*8 + g];
                bfr[1] = Vs[cur][(kk*8+tg+4)*VSTR + nt*8 + g];
                mma8(o[nt], pf, bfr);
            }
        }
    }

    // ---- finalize + write out [B,S,D] ----
    float inv0 = 1.f / l0, inv1 = 1.f / l1;
    int sr0 = q0 + qr + g;
    int sr1 = sr0 + 8;
    #pragma unroll
    for (int nt = 0; nt < 8; nt++) {
        int d = nt*8 + 2*tg;
        float2 v0 = { o[nt][0]*inv0, o[nt][1]*inv0 };
        float2 v1 = { o[nt][2]*inv1, o[nt][3]*inv1 };
        *(float2*)(out + ((size_t)b*S_ + sr0)*D_ + h*HD_ + d) = v0;
        *(float2*)(out + ((size_t)b*S_ + sr1)*D_ + h*HD_ + d) = v1;
    }
}

// ---------------- launch ----------------
extern "C" void kernel_launch(void* const* d_in, const int* in_sizes, int n_in,
                              void* d_out, int out_size) {
    const float* x    = (const float*)d_in[0];
    const float* wq_w = (const float*)d_in[1];
    const float* wq_b = (const float*)d_in[2];
    const float* wk_w = (const float*)d_in[3];
    const float* wk_b = (const float*)d_in[4];
    const float* wv_w = (const float*)d_in[5];
    const float* wv_b = (const float*)d_in[6];
    float* out = (float*)d_out;

    rope_table_kernel<<<(S_*(HD_/2) + 255)/256, 256>>>();

    dim3 gg(D_/128, (B_*S_)/128, 3);
    qkv_gemm_kernel<<<gg, 256>>>(x, wq_w, wq_b, wk_w, wk_b, wv_w, wv_b);

    cudaFuncSetAttribute(attn_kernel,
                         cudaFuncAttributeMaxDynamicSharedMemorySize,
                         ATTN_SMEM_BYTES);
    dim3 ga(S_/128, H_, B_);
    attn_kernel<<<ga, 256, ATTN_SMEM_BYTES>>>(out);
}

// round 6
// speedup vs baseline: 1.1578x; 1.1578x over previous
#include <cuda_runtime.h>
#include <math.h>

#define B_  2
#define S_  2048
#define D_  1024
#define H_  16
#define HD_ 64

// ---------------- scratch (no allocs allowed) ----------------
// g_q / g_k / g_v hold tf32 BIT PATTERNS (written by GEMM epilogue).
// g_q is additionally pre-scaled by 1/sqrt(HD).
__device__ float g_q[B_*H_*S_*HD_];
__device__ float g_k[B_*H_*S_*HD_];
__device__ float g_v[B_*H_*S_*HD_];
__device__ float g_cos[S_*(HD_/2)];
__device__ float g_sin[S_*(HD_/2)];

// ---------------- helpers ----------------
__device__ __forceinline__ unsigned f2tf(float f) {
    unsigned u;
    asm("cvt.rna.tf32.f32 %0, %1;" : "=r"(u) : "f"(f));
    return u;
}

__device__ __forceinline__ void mma8(float* c, const unsigned* a, const unsigned* b) {
    asm volatile(
        "mma.sync.aligned.m16n8k8.row.col.f32.tf32.tf32.f32 "
        "{%0,%1,%2,%3},{%4,%5,%6,%7},{%8,%9},{%0,%1,%2,%3};"
        : "+f"(c[0]), "+f"(c[1]), "+f"(c[2]), "+f"(c[3])
        : "r"(a[0]), "r"(a[1]), "r"(a[2]), "r"(a[3]),
          "r"(b[0]), "r"(b[1]));
}

__device__ __forceinline__ void cpa16(void* smem, const void* gmem) {
    unsigned s = (unsigned)__cvta_generic_to_shared(smem);
    asm volatile("cp.async.cg.shared.global [%0], [%1], 16;" :: "r"(s), "l"(gmem));
}
#define CPA_COMMIT() asm volatile("cp.async.commit_group;")
#define CPA_WAIT0()  asm volatile("cp.async.wait_group 0;")

// ---------------- RoPE table ----------------
__global__ void rope_table_kernel() {
    int idx = blockIdx.x * blockDim.x + threadIdx.x;
    if (idx < S_ * (HD_/2)) {
        int s = idx >> 5;
        int p = idx & 31;
        double theta = exp2(-(double)p * (13.287712379549449 / 32.0));
        double ang = (double)s * theta;
        const double twopi = 6.283185307179586476925286766559;
        double r = ang - twopi * floor(ang / twopi);
        float sn, cs;
        sincosf((float)r, &sn, &cs);
        g_cos[idx] = cs;
        g_sin[idx] = sn;
    }
}

// ---------------- QKV GEMM (tf32 mma, reg-prefetch double-buffered smem) ----------------
// 128x128 tile, BK=16, 256 threads = 8 warps, warp tile 64x32 (4 m16 x 4 n8).
// Epilogue writes tf32 bit patterns (Q pre-scaled by 0.125, Q/K RoPE'd).
#define GSTR 20

__global__ __launch_bounds__(256, 2) void qkv_gemm_kernel(
    const float* __restrict__ x,
    const float* __restrict__ wq, const float* __restrict__ bq,
    const float* __restrict__ wk, const float* __restrict__ bk,
    const float* __restrict__ wv, const float* __restrict__ bv)
{
    const int mat = blockIdx.z;
    const float* __restrict__ W    = (mat==0) ? wq : (mat==1 ? wk : wv);
    const float* __restrict__ bias = (mat==0) ? bq : (mat==1 ? bk : bv);
    float* out = (mat==0) ? g_q : (mat==1 ? g_k : g_v);

    __shared__ unsigned As[2][128*GSTR];
    __shared__ unsigned Bs[2][128*GSTR];

    const int tid  = threadIdx.x;
    const int warp = tid >> 5;
    const int lane = tid & 31;
    const int g    = lane >> 2;
    const int tg   = lane & 3;
    const int wm   = warp & 1;
    const int wn   = warp >> 1;

    const int m0 = blockIdx.y * 128;
    const int n0 = blockIdx.x * 128;

    int am[2], ac[2];
    {
        int f0 = tid;       am[0] = f0 >> 2; ac[0] = (f0 & 3) * 4;
        int f1 = tid + 256; am[1] = f1 >> 2; ac[1] = (f1 & 3) * 4;
    }
    const float* aG[2] = { x + (size_t)(m0 + am[0])*D_ + ac[0],
                           x + (size_t)(m0 + am[1])*D_ + ac[1] };
    const float* bG[2] = { W + (size_t)(n0 + am[0])*D_ + ac[0],
                           W + (size_t)(n0 + am[1])*D_ + ac[1] };

    float acc[4][4][4];
    #pragma unroll
    for (int i = 0; i < 4; i++)
        #pragma unroll
        for (int j = 0; j < 4; j++)
            #pragma unroll
            for (int q = 0; q < 4; q++) acc[i][j][q] = 0.f;

    // stage 0
    float4 pa[2], pb[2];
    #pragma unroll
    for (int i = 0; i < 2; i++) {
        pa[i] = *(const float4*)(aG[i]);
        pb[i] = *(const float4*)(bG[i]);
    }
    #pragma unroll
    for (int i = 0; i < 2; i++) {
        uint4 ua = { f2tf(pa[i].x), f2tf(pa[i].y), f2tf(pa[i].z), f2tf(pa[i].w) };
        uint4 ub = { f2tf(pb[i].x), f2tf(pb[i].y), f2tf(pb[i].z), f2tf(pb[i].w) };
        *(uint4*)&As[0][am[i]*GSTR + ac[i]] = ua;
        *(uint4*)&Bs[0][am[i]*GSTR + ac[i]] = ub;
    }
    __syncthreads();

    int cur = 0;
    for (int k0 = 0; k0 < D_; k0 += 16) {
        const bool more = (k0 + 16 < D_);
        if (more) {
            #pragma unroll
            for (int i = 0; i < 2; i++) {
                pa[i] = *(const float4*)(aG[i] + k0 + 16);
                pb[i] = *(const float4*)(bG[i] + k0 + 16);
            }
        }

        #pragma unroll
        for (int kk = 0; kk < 2; kk++) {
            const int k = kk * 8;
            unsigned af[4][4], bf[4][2];
            #pragma unroll
            for (int mt = 0; mt < 4; mt++) {
                int rm = wm*64 + mt*16;
                af[mt][0] = As[cur][(rm+g  )*GSTR + k + tg];
                af[mt][1] = As[cur][(rm+g+8)*GSTR + k + tg];
                af[mt][2] = As[cur][(rm+g  )*GSTR + k + tg + 4];
                af[mt][3] = As[cur][(rm+g+8)*GSTR + k + tg + 4];
            }
            #pragma unroll
            for (int nt = 0; nt < 4; nt++) {
                int cn = wn*32 + nt*8;
                bf[nt][0] = Bs[cur][(cn+g)*GSTR + k + tg];
                bf[nt][1] = Bs[cur][(cn+g)*GSTR + k + tg + 4];
            }
            #pragma unroll
            for (int mt = 0; mt < 4; mt++)
                #pragma unroll
                for (int nt = 0; nt < 4; nt++)
                    mma8(acc[mt][nt], af[mt], bf[nt]);
        }

        if (more) {
            #pragma unroll
            for (int i = 0; i < 2; i++) {
                uint4 ua = { f2tf(pa[i].x), f2tf(pa[i].y), f2tf(pa[i].z), f2tf(pa[i].w) };
                uint4 ub = { f2tf(pb[i].x), f2tf(pb[i].y), f2tf(pb[i].z), f2tf(pb[i].w) };
                *(uint4*)&As[cur^1][am[i]*GSTR + ac[i]] = ua;
                *(uint4*)&Bs[cur^1][am[i]*GSTR + ac[i]] = ub;
            }
        }
        __syncthreads();
        cur ^= 1;
    }

    // epilogue: bias + (RoPE + prescale for Q), tf32 bit patterns to [B,H,S,HD]
    const float qsc = (mat == 0) ? 0.125f : 1.0f;
    #pragma unroll
    for (int mt = 0; mt < 4; mt++) {
        #pragma unroll
        for (int half = 0; half < 2; half++) {
            int r  = m0 + wm*64 + mt*16 + g + half*8;
            int b_ = r >> 11;
            int s  = r & (S_ - 1);
            #pragma unroll
            for (int nt = 0; nt < 4; nt++) {
                int n  = n0 + wn*32 + nt*8 + 2*tg;
                float c0 = (acc[mt][nt][half*2]   + bias[n])   * qsc;
                float c1 = (acc[mt][nt][half*2+1] + bias[n+1]) * qsc;
                int h = n >> 6;
                int d = n & 63;
                float* dst = out + ((((size_t)b_*H_ + h)*S_ + s)*HD_ + d);
                float r0, r1;
                if (mat < 2) {
                    int p = d >> 1;
                    float cs = g_cos[s*32 + p];
                    float sn = g_sin[s*32 + p];
                    r0 = c0*cs - c1*sn;
                    r1 = c0*sn + c1*cs;
                } else {
                    r0 = c0; r1 = c1;
                }
                float2 v = { __uint_as_float(f2tf(r0)), __uint_as_float(f2tf(r1)) };
                *(float2*)dst = v;
            }
        }
    }
}

// ---------------- Flash attention (tf32 mma, double-buffered cp.async, no cvt) ----------------
// Block: 128 queries of one (b,h). 8 warps, each owns a 16-row slab. K tile 64.
// g_q/g_k/g_v already hold tf32 bit patterns; Q already pre-scaled.
#define PSTR 68
#define KSTR 68
#define VSTR 72
#define ATTN_SMEM_WORDS (128*PSTR + 2*64*KSTR + 2*64*VSTR)
#define ATTN_SMEM_BYTES (ATTN_SMEM_WORDS * 4)

__global__ __launch_bounds__(256, 2) void attn_kernel(float* __restrict__ out)
{
    extern __shared__ unsigned sm[];
    unsigned* Ps = sm;                              // [128][PSTR] tf32 (Q then P)
    unsigned* Ks[2] = { Ps + 128*PSTR, Ps + 128*PSTR + 64*KSTR };
    unsigned* Vs[2] = { Ks[1] + 64*KSTR, Ks[1] + 64*KSTR + 64*VSTR };

    const int tid  = threadIdx.x;
    const int warp = tid >> 5;
    const int lane = tid & 31;
    const int g    = lane >> 2;
    const int tg   = lane & 3;
    const int qr   = warp * 16;

    const int q0 = blockIdx.x * 128;
    const int h  = blockIdx.y;
    const int b  = blockIdx.z;

    const float* qbase = g_q + (((size_t)b*H_ + h)*S_) * HD_;
    const float* kbase = g_k + (((size_t)b*H_ + h)*S_) * HD_;
    const float* vbase = g_v + (((size_t)b*H_ + h)*S_) * HD_;

    int krow[4], kcol[4];
    #pragma unroll
    for (int r = 0; r < 4; r++) {
        int f = tid + 256*r;
        krow[r] = f >> 4;
        kcol[r] = (f & 15) * 4;
    }

    // tile 0 into buffer 0 (overlaps Q staging)
    #pragma unroll
    for (int r = 0; r < 4; r++) {
        int off = (tid + 256*r) * 4;
        cpa16(&Ks[0][krow[r]*KSTR + kcol[r]], kbase + off);
        cpa16(&Vs[0][krow[r]*VSTR + kcol[r]], vbase + off);
    }
    CPA_COMMIT();

    // ---- stage Q bits into Ps (already tf32 + pre-scaled) ----
    #pragma unroll
    for (int r = 0; r < 8; r++) {
        int f   = tid + 256*r;
        int row = f >> 4;
        int col = (f & 15) * 4;
        uint4 u = *(const uint4*)(qbase + (size_t)(q0+row)*HD_ + col);
        *(uint4*)&Ps[row*PSTR + col] = u;
    }
    __syncthreads();

    unsigned qf[8][4];
    #pragma unroll
    for (int kk = 0; kk < 8; kk++) {
        qf[kk][0] = Ps[(qr+g  )*PSTR + kk*8 + tg];
        qf[kk][1] = Ps[(qr+g+8)*PSTR + kk*8 + tg];
        qf[kk][2] = Ps[(qr+g  )*PSTR + kk*8 + tg + 4];
        qf[kk][3] = Ps[(qr+g+8)*PSTR + kk*8 + tg + 4];
    }

    float o[8][4];
    #pragma unroll
    for (int nt = 0; nt < 8; nt++)
        #pragma unroll
        for (int q = 0; q < 4; q++) o[nt][q] = 0.f;
    float m0r = -INFINITY, m1r = -INFINITY, l0 = 0.f, l1 = 0.f;

    for (int kt = 0; kt < S_/64; kt++) {
        const int cur = kt & 1;
        CPA_WAIT0();
        __syncthreads();   // tile kt visible; prior compute on buffer cur done; qf loads done

        // prefetch tile kt+1 into other buffer — overlaps all compute below
        if (kt + 1 < S_/64) {
            const float* kb = kbase + (size_t)(kt+1)*4096;
            const float* vb = vbase + (size_t)(kt+1)*4096;
            #pragma unroll
            for (int r = 0; r < 4; r++) {
                int off = (tid + 256*r) * 4;
                cpa16(&Ks[cur^1][krow[r]*KSTR + kcol[r]], kb + off);
                cpa16(&Vs[cur^1][krow[r]*VSTR + kcol[r]], vb + off);
            }
            CPA_COMMIT();
        }

        // ---- S = Q K^T ----
        float s[8][4];
        #pragma unroll
        for (int nt = 0; nt < 8; nt++)
            #pragma unroll
            for (int q = 0; q < 4; q++) s[nt][q] = 0.f;

        #pragma unroll
        for (int nt = 0; nt < 8; nt++) {
            #pragma unroll
            for (int kk = 0; kk < 8; kk++) {
                unsigned bfr[2];
                bfr[0] = Ks[cur][(nt*8+g)*KSTR + kk*8 + tg];
                bfr[1] = Ks[cur][(nt*8+g)*KSTR + kk*8 + tg + 4];
                mma8(s[nt], qf[kk], bfr);
            }
        }

        // ---- online softmax ----
        float mx0 = -INFINITY, mx1 = -INFINITY;
        #pragma unroll
        for (int nt = 0; nt < 8; nt++) {
            mx0 = fmaxf(mx0, fmaxf(s[nt][0], s[nt][1]));
            mx1 = fmaxf(mx1, fmaxf(s[nt][2], s[nt][3]));
        }
        mx0 = fmaxf(mx0, __shfl_xor_sync(0xffffffffu, mx0, 1));
        mx0 = fmaxf(mx0, __shfl_xor_sync(0xffffffffu, mx0, 2));
        mx1 = fmaxf(mx1, __shfl_xor_sync(0xffffffffu, mx1, 1));
        mx1 = fmaxf(mx1, __shfl_xor_sync(0xffffffffu, mx1, 2));

        float nm0 = fmaxf(m0r, mx0), nm1 = fmaxf(m1r, mx1);
        float f0 = __expf(m0r - nm0), f1 = __expf(m1r - nm1);
        m0r = nm0; m1r = nm1;

        float rs0 = 0.f, rs1 = 0.f;
        #pragma unroll
        for (int nt = 0; nt < 8; nt++) {
            s[nt][0] = __expf(s[nt][0] - nm0);
            s[nt][1] = __expf(s[nt][1] - nm0);
            s[nt][2] = __expf(s[nt][2] - nm1);
            s[nt][3] = __expf(s[nt][3] - nm1);
            rs0 += s[nt][0] + s[nt][1];
            rs1 += s[nt][2] + s[nt][3];
            o[nt][0] *= f0; o[nt][1] *= f0;
            o[nt][2] *= f1; o[nt][3] *= f1;
        }
        rs0 += __shfl_xor_sync(0xffffffffu, rs0, 1);
        rs0 += __shfl_xor_sync(0xffffffffu, rs0, 2);
        rs1 += __shfl_xor_sync(0xffffffffu, rs1, 1);
        rs1 += __shfl_xor_sync(0xffffffffu, rs1, 2);
        l0 = l0*f0 + rs0;
        l1 = l1*f1 + rs1;

        // ---- store P (tf32) for re-fragmenting (within-warp slab only) ----
        #pragma unroll
        for (int nt = 0; nt < 8; nt++) {
            Ps[(qr+g  )*PSTR + nt*8 + 2*tg    ] = f2tf(s[nt][0]);
            Ps[(qr+g  )*PSTR + nt*8 + 2*tg + 1] = f2tf(s[nt][1]);
            Ps[(qr+g+8)*PSTR + nt*8 + 2*tg    ] = f2tf(s[nt][2]);
            Ps[(qr+g+8)*PSTR + nt*8 + 2*tg + 1] = f2tf(s[nt][3]);
        }
        __syncwarp();

        // ---- O += P V ----
        #pragma unroll
        for (int kk = 0; kk < 8; kk++) {
            unsigned pf[4];
            pf[0] = Ps[(qr+g  )*PSTR + kk*8 + tg];
            pf[1] = Ps[(qr+g+8)*PSTR + kk*8 + tg];
            pf[2] = Ps[(qr+g  )*PSTR + kk*8 + tg + 4];
            pf[3] = Ps[(qr+g+8)*PSTR + kk*8 + tg + 4];
            #pragma unroll
            for (int nt = 0; nt < 8; nt++) {
                unsigned bfr[2];
                bfr[0] = Vs[cur][(kk*8+tg  )*VSTR + nt*8 + g];
                bfr[1] = Vs[cur][(kk*8+tg+4)*VSTR + nt*8 + g];
                mma8(o[nt], pf, bfr);
            }
        }
    }

    // ---- finalize + write out [B,S,D] ----
    float inv0 = 1.f / l0, inv1 = 1.f / l1;
    int sr0 = q0 + qr + g;
    int sr1 = sr0 + 8;
    #pragma unroll
    for (int nt = 0; nt < 8; nt++) {
        int d = nt*8 + 2*tg;
        float2 v0 = { o[nt][0]*inv0, o[nt][1]*inv0 };
        float2 v1 = { o[nt][2]*inv1, o[nt][3]*inv1 };
        *(float2*)(out + ((size_t)b*S_ + sr0)*D_ + h*HD_ + d) = v0;
        *(float2*)(out + ((size_t)b*S_ + sr1)*D_ + h*HD_ + d) = v1;
    }
}

// ---------------- launch ----------------
extern "C" void kernel_launch(void* const* d_in, const int* in_sizes, int n_in,
                              void* d_out, int out_size) {
    const float* x    = (const float*)d_in[0];
    const float* wq_w = (const float*)d_in[1];
    const float* wq_b = (const float*)d_in[2];
    const float* wk_w = (const float*)d_in[3];
    const float* wk_b = (const float*)d_in[4];
    const float* wv_w = (const float*)d_in[5];
    const float* wv_b = (const float*)d_in[6];
    float* out = (float*)d_out;

    rope_table_kernel<<<(S_*(HD_/2) + 255)/256, 256>>>();

    dim3 gg(D_/128, (B_*S_)/128, 3);
    qkv_gemm_kernel<<<gg, 256>>>(x, wq_w, wq_b, wk_w, wk_b, wv_w, wv_b);

    cudaFuncSetAttribute(attn_kernel,
                         cudaFuncAttributeMaxDynamicSharedMemorySize,
                         ATTN_SMEM_BYTES);
    dim3 ga(S_/128, H_, B_);
    attn_kernel<<<ga, 256, ATTN_SMEM_BYTES>>>(out);
}